// round 9
// baseline (speedup 1.0000x reference)
#include <cuda_runtime.h>
#include <math.h>
#include <stdint.h>

#define N_NODES 10000
#define N_EDGES 160000
#define FIN     256
#define HID     128
#define H1      5
#define H3      3
#define NGRAPH  64
#define NCLS    10
#define D1      (H1*HID)   /* 640 */
#define ETOT    (N_EDGES + N_NODES)

// ---------------- device scratch (no allocation allowed) ----------------
__device__ float g_h  [N_NODES * D1];
__device__ float g_x1 [N_NODES * D1];
__device__ float g_x2 [N_NODES * D1];
__device__ float g_als[N_NODES * H1];
__device__ float g_ald[N_NODES * H1];
__device__ float g_x3 [N_NODES * HID];
__device__ float g_pool[NGRAPH * HID];
__device__ float g_cnt [NGRAPH];
// CSR scratch
__device__ int g_deg[N_NODES];
__device__ int g_off[N_NODES + 1];
__device__ int g_cur[N_NODES];
__device__ int g_col[ETOT];

// ---------------- fills ----------------
__global__ void fill_kernel(float* p, float v, int n) {
    int i = blockIdx.x * blockDim.x + threadIdx.x;
    if (i < n) p[i] = v;
}
__global__ void fill_int_kernel(int* p, int v, int n) {
    int i = blockIdx.x * blockDim.x + threadIdx.x;
    if (i < n) p[i] = v;
}

// ---------------- CSR build: histogram -> scan -> scatter ----------------
__global__ void hist_kernel(const int* __restrict__ dst, int* __restrict__ deg) {
    int i = blockIdx.x * blockDim.x + threadIdx.x;
    if (i >= ETOT) return;
    int d = (i < N_EDGES) ? dst[i] : (i - N_EDGES);
    atomicAdd(&deg[d], 1);
}

__global__ void scan_kernel(const int* __restrict__ deg, int* __restrict__ off,
                            int* __restrict__ cur) {
    __shared__ int part[1024];
    int t = threadIdx.x;
    const int CH = (N_NODES + 1023) / 1024;   // 10
    int base = t * CH;
    int s = 0;
    for (int i = 0; i < CH; i++) {
        int idx = base + i;
        if (idx < N_NODES) s += deg[idx];
    }
    part[t] = s;
    __syncthreads();
    for (int o = 1; o < 1024; o <<= 1) {
        int v = (t >= o) ? part[t - o] : 0;
        __syncthreads();
        part[t] += v;
        __syncthreads();
    }
    int run = (t == 0) ? 0 : part[t - 1];
    for (int i = 0; i < CH; i++) {
        int idx = base + i;
        if (idx < N_NODES) {
            off[idx] = run;
            cur[idx] = run;
            run += deg[idx];
        }
    }
    if (t == 1023) off[N_NODES] = ETOT;
}

__global__ void scatter_kernel(const int* __restrict__ src, const int* __restrict__ dst,
                               int* __restrict__ cur, int* __restrict__ colarr) {
    int i = blockIdx.x * blockDim.x + threadIdx.x;
    if (i >= ETOT) return;
    int d, s;
    if (i < N_EDGES) { s = src[i]; d = dst[i]; } else { s = d = i - N_EDGES; }
    int slot = atomicAdd(&cur[d], 1);
    colarr[slot] = s;
}

// ---------------- tf32 helpers ----------------
__device__ __forceinline__ float to_tf32(float x) {
    uint32_t r;
    asm("cvt.rna.tf32.f32 %0, %1;" : "=r"(r) : "f"(x));
    return __uint_as_float(r);
}

__device__ __forceinline__ void mma_tf32(float* c, const uint32_t* a,
                                         uint32_t b0, uint32_t b1) {
    asm volatile("mma.sync.aligned.m16n8k8.row.col.f32.tf32.tf32.f32 "
        "{%0,%1,%2,%3}, {%4,%5,%6,%7}, {%8,%9}, {%0,%1,%2,%3};"
        : "+f"(c[0]), "+f"(c[1]), "+f"(c[2]), "+f"(c[3])
        : "r"(a[0]), "r"(a[1]), "r"(a[2]), "r"(a[3]), "r"(b0), "r"(b1));
}

// ---------------- tensor-core tf32 GEMM, double-buffered ----------------
// C[M,Nd] = A[M,K] @ B[K,Nd]; BM=BN=128, BK=16; 8 warps; warp tile 32x64.
// Requires Nd % 128 == 0, K % 16 == 0.
#define SSTR 136   /* smem row stride (floats): conflict-free frag loads */
__global__ void __launch_bounds__(256)
mma_gemm_kernel(const float* __restrict__ A, const float* __restrict__ B,
                float* __restrict__ C, int M, int K, int Nd) {
    __shared__ float As[2][16][SSTR];   // As[buf][k][m]
    __shared__ float Bs[2][16][SSTR];   // Bs[buf][k][n]
    int tid = threadIdx.x;
    int lane = tid & 31;
    int wid = tid >> 5;
    int wm = (wid & 3) * 32;   // warp row offset within block
    int wn = (wid >> 2) * 64;  // warp col offset within block
    int rowBase = blockIdx.y * 128;
    int colBase = blockIdx.x * 128;
    int g = lane >> 2, t4 = lane & 3;

    // load mappings (each thread: 2 float4 of A, 2 float4 of B)
    int ar0 = tid >> 1;                 // wrong for it-loop; recompute per it
    (void)ar0;

    float c[2][8][4];
    #pragma unroll
    for (int mt = 0; mt < 2; mt++)
        #pragma unroll
        for (int nt = 0; nt < 8; nt++)
            #pragma unroll
            for (int i = 0; i < 4; i++) c[mt][nt][i] = 0.f;

    float4 aR[2], bR[2];

    auto load_g = [&](int k0) {
        #pragma unroll
        for (int it = 0; it < 2; it++) {
            int f = tid + it * 256;        // 0..511 float4 slots
            int row = f >> 2, q = f & 3;
            float4 a4 = make_float4(0.f, 0.f, 0.f, 0.f);
            int grow = rowBase + row;
            if (grow < M) a4 = *(const float4*)&A[(size_t)grow * K + k0 + q * 4];
            aR[it] = a4;
            int kr = f >> 5, c4 = (f & 31) * 4;
            bR[it] = *(const float4*)&B[(size_t)(k0 + kr) * Nd + colBase + c4];
        }
    };
    auto store_s = [&](int buf) {
        #pragma unroll
        for (int it = 0; it < 2; it++) {
            int f = tid + it * 256;
            int row = f >> 2, q = f & 3;
            As[buf][q * 4 + 0][row] = to_tf32(aR[it].x);
            As[buf][q * 4 + 1][row] = to_tf32(aR[it].y);
            As[buf][q * 4 + 2][row] = to_tf32(aR[it].z);
            As[buf][q * 4 + 3][row] = to_tf32(aR[it].w);
            int kr = f >> 5, c4 = (f & 31) * 4;
            float4 b4 = bR[it];
            b4.x = to_tf32(b4.x); b4.y = to_tf32(b4.y);
            b4.z = to_tf32(b4.z); b4.w = to_tf32(b4.w);
            *(float4*)&Bs[buf][kr][c4] = b4;
        }
    };

    load_g(0);
    store_s(0);
    __syncthreads();
    int buf = 0;

    for (int k0 = 0; k0 < K; k0 += 16) {
        bool more = (k0 + 16) < K;
        if (more) load_g(k0 + 16);
        #pragma unroll
        for (int kk = 0; kk < 16; kk += 8) {
            uint32_t a[2][4];
            #pragma unroll
            for (int mt = 0; mt < 2; mt++) {
                int r0 = wm + mt * 16 + g;
                a[mt][0] = __float_as_uint(As[buf][kk + t4    ][r0    ]);
                a[mt][1] = __float_as_uint(As[buf][kk + t4    ][r0 + 8]);
                a[mt][2] = __float_as_uint(As[buf][kk + t4 + 4][r0    ]);
                a[mt][3] = __float_as_uint(As[buf][kk + t4 + 4][r0 + 8]);
            }
            #pragma unroll
            for (int nt = 0; nt < 8; nt++) {
                int cn = wn + nt * 8 + g;
                uint32_t b0 = __float_as_uint(Bs[buf][kk + t4    ][cn]);
                uint32_t b1 = __float_as_uint(Bs[buf][kk + t4 + 4][cn]);
                mma_tf32(c[0][nt], a[0], b0, b1);
                mma_tf32(c[1][nt], a[1], b0, b1);
            }
        }
        if (more) {
            store_s(buf ^ 1);
            __syncthreads();
        }
        buf ^= 1;
    }
    // epilogue
    #pragma unroll
    for (int mt = 0; mt < 2; mt++) {
        int r0 = rowBase + wm + mt * 16 + g;
        #pragma unroll
        for (int nt = 0; nt < 8; nt++) {
            int cc = colBase + wn + nt * 8 + (t4 << 1);
            if (r0 < M)
                *(float2*)&C[(size_t)r0 * Nd + cc] = make_float2(c[mt][nt][0], c[mt][nt][1]);
            if (r0 + 8 < M)
                *(float2*)&C[(size_t)(r0 + 8) * Nd + cc] = make_float2(c[mt][nt][2], c[mt][nt][3]);
        }
    }
}

// ---------------- per-(node,head) attention logits ----------------
__global__ void attn_logits_kernel(const float* __restrict__ h,
                                   const float* __restrict__ a_s,
                                   const float* __restrict__ a_d,
                                   float* __restrict__ als, float* __restrict__ ald,
                                   int N, int H) {
    int w = (blockIdx.x * blockDim.x + threadIdx.x) >> 5;
    int lane = threadIdx.x & 31;
    if (w >= N * H) return;
    int n = w / H, hh = w % H;
    const float* hp = h + ((size_t)n * H + hh) * HID;
    float s1 = 0.f, s2 = 0.f;
    #pragma unroll
    for (int c = lane; c < HID; c += 32) {
        float v = hp[c];
        s1 += v * a_s[hh * HID + c];
        s2 += v * a_d[hh * HID + c];
    }
    #pragma unroll
    for (int o = 16; o > 0; o >>= 1) {
        s1 += __shfl_xor_sync(0xffffffffu, s1, o);
        s2 += __shfl_xor_sync(0xffffffffu, s2, o);
    }
    if (lane == 0) { als[w] = s1; ald[w] = s2; }
}

// ---------------- fused CSR softmax aggregation + finalize ----------------
// One warp per node. exp computed once per edge (lane-strided), broadcast via
// per-warp smem stage (replaces 2x SHFL in the accumulate loop).
// MODE 1: out = elu(agg + b)                 [D = H*HID]
// MODE 2: out = elu(xres + agg + b)          [D = H*HID]
// MODE 3: out = mean_heads(agg) + b          [D = HID]
template<int H, int MODE>
__global__ void __launch_bounds__(256)
gat_agg_kernel(const int* __restrict__ off, const int* __restrict__ col,
               const float* __restrict__ als, const float* __restrict__ ald,
               const float* __restrict__ h, const float* __restrict__ b,
               const float* __restrict__ xres, float* __restrict__ outbuf) {
    __shared__ float2 stage[8][32];
    int w = threadIdx.x >> 5;
    int node = (blockIdx.x * blockDim.x + threadIdx.x) >> 5;
    int lane = threadIdx.x & 31;
    if (node >= N_NODES) return;
    int beg = off[node], end = off[node + 1];

    float4 hacc = make_float4(0.f, 0.f, 0.f, 0.f);   // MODE 3 head-mean accumulator

    #pragma unroll
    for (int hh = 0; hh < H; hh++) {
        float ald_d = __ldg(&ald[node * H + hh]);
        // pass 1: max (lane-strided)
        float mx = -1e30f;
        for (int j = beg + lane; j < end; j += 32) {
            float v = __ldg(&als[col[j] * H + hh]) + ald_d;
            v = v > 0.f ? v : 0.2f * v;
            mx = fmaxf(mx, v);
        }
        #pragma unroll
        for (int o = 16; o > 0; o >>= 1)
            mx = fmaxf(mx, __shfl_xor_sync(0xffffffffu, mx, o));
        // pass 2: chunks of 32 edges; lane computes one exp; smem broadcast
        float4 acc = make_float4(0.f, 0.f, 0.f, 0.f);
        float ssum = 0.f;
        for (int j0 = beg; j0 < end; j0 += 32) {
            int jj = j0 + lane;
            float ex = 0.f;
            int sc = 0;
            if (jj < end) {
                sc = col[jj];
                float v = __ldg(&als[sc * H + hh]) + ald_d;
                v = v > 0.f ? v : 0.2f * v;
                ex = __expf(v - mx);
            }
            ssum += ex;
            stage[w][lane] = make_float2(ex, __int_as_float(sc));
            __syncwarp();
            int cnt = end - j0; if (cnt > 32) cnt = 32;
            for (int t = 0; t < cnt; t++) {
                float2 e = stage[w][t];
                float exb = e.x;
                int sb = __float_as_int(e.y);
                float4 hv = ((const float4*)(h + ((size_t)sb * H + hh) * HID))[lane];
                acc.x += exb * hv.x;
                acc.y += exb * hv.y;
                acc.z += exb * hv.z;
                acc.w += exb * hv.w;
            }
            __syncwarp();
        }
        #pragma unroll
        for (int o = 16; o > 0; o >>= 1)
            ssum += __shfl_xor_sync(0xffffffffu, ssum, o);
        float inv = 1.f / (ssum + 1e-16f);
        acc.x *= inv; acc.y *= inv; acc.z *= inv; acc.w *= inv;

        if (MODE == 3) {
            hacc.x += acc.x; hacc.y += acc.y; hacc.z += acc.z; hacc.w += acc.w;
        } else {
            int r = hh * HID + lane * 4;
            float4 bb = *(const float4*)&b[r];
            size_t idx = (size_t)node * (H * HID) + r;
            float4 v4;
            if (MODE == 2) {
                float4 xr = *(const float4*)&xres[idx];
                v4.x = xr.x + acc.x + bb.x;
                v4.y = xr.y + acc.y + bb.y;
                v4.z = xr.z + acc.z + bb.z;
                v4.w = xr.w + acc.w + bb.w;
            } else {
                v4.x = acc.x + bb.x;
                v4.y = acc.y + bb.y;
                v4.z = acc.z + bb.z;
                v4.w = acc.w + bb.w;
            }
            v4.x = v4.x > 0.f ? v4.x : (expf(v4.x) - 1.f);
            v4.y = v4.y > 0.f ? v4.y : (expf(v4.y) - 1.f);
            v4.z = v4.z > 0.f ? v4.z : (expf(v4.z) - 1.f);
            v4.w = v4.w > 0.f ? v4.w : (expf(v4.w) - 1.f);
            *(float4*)&outbuf[idx] = v4;
        }
    }
    if (MODE == 3) {
        int r = lane * 4;
        float4 bb = *(const float4*)&b[r];
        const float s = 1.f / (float)H;
        float4 v4 = make_float4(hacc.x * s + bb.x, hacc.y * s + bb.y,
                                hacc.z * s + bb.z, hacc.w * s + bb.w);
        *(float4*)&outbuf[(size_t)node * HID + r] = v4;
    }
}

// ---------------- global mean pool ----------------
__global__ void pool_kernel(const float* __restrict__ x3, const int* __restrict__ batch,
                            float* __restrict__ pool, float* __restrict__ cnt) {
    int i = blockIdx.x * blockDim.x + threadIdx.x;
    if (i >= N_NODES * HID) return;
    int n = i / HID, c = i % HID;
    int g = batch[n];
    atomicAdd(&pool[(size_t)g * HID + c], x3[i]);
    if (c == 0) atomicAdd(&cnt[g], 1.f);
}

// ---------------- classifier head + log_softmax ----------------
__global__ void head_kernel(const float* __restrict__ pool, const float* __restrict__ cnt,
                            const float* __restrict__ Wc, const float* __restrict__ bc,
                            float* __restrict__ out) {
    __shared__ float sl[NGRAPH][NCLS];
    __shared__ float lse[NGRAPH];
    int tid = threadIdx.x;               // 640 threads
    int g = tid / NCLS, k = tid % NCLS;
    float c = cnt[g]; c = c < 1.f ? 1.f : c;
    float acc = bc[k];
    #pragma unroll 8
    for (int j = 0; j < HID; j++)
        acc += (pool[(size_t)g * HID + j] / c) * Wc[j * NCLS + k];
    sl[g][k] = acc;
    out[g * NCLS + k] = acc;             // logits
    __syncthreads();
    if (k == 0) {
        float mx = sl[g][0];
        #pragma unroll
        for (int j = 1; j < NCLS; j++) mx = fmaxf(mx, sl[g][j]);
        float s = 0.f;
        #pragma unroll
        for (int j = 0; j < NCLS; j++) s += expf(sl[g][j] - mx);
        lse[g] = mx + logf(s);
    }
    __syncthreads();
    out[NGRAPH * NCLS + g * NCLS + k] = sl[g][k] - lse[g];   // log_softmax
}

extern "C" void kernel_launch(void* const* d_in, const int* in_sizes, int n_in,
                              void* d_out, int out_size) {
    const float* x     = (const float*)d_in[0];
    const int*   ei    = (const int*)  d_in[1];
    const int*   batch = (const int*)  d_in[2];
    const float* W1  = (const float*)d_in[3];
    const float* a1s = (const float*)d_in[4];
    const float* a1d = (const float*)d_in[5];
    const float* b1  = (const float*)d_in[6];
    const float* W2  = (const float*)d_in[7];
    const float* a2s = (const float*)d_in[8];
    const float* a2d = (const float*)d_in[9];
    const float* b2  = (const float*)d_in[10];
    const float* W3  = (const float*)d_in[11];
    const float* a3s = (const float*)d_in[12];
    const float* a3d = (const float*)d_in[13];
    const float* b3  = (const float*)d_in[14];
    const float* Wc  = (const float*)d_in[15];
    const float* bc  = (const float*)d_in[16];
    float* out = (float*)d_out;

    float *h, *x1, *x2, *als, *ald, *x3, *pool, *cnt;
    int *deg, *off, *cur, *col;
    cudaGetSymbolAddress((void**)&h,    g_h);
    cudaGetSymbolAddress((void**)&x1,   g_x1);
    cudaGetSymbolAddress((void**)&x2,   g_x2);
    cudaGetSymbolAddress((void**)&als,  g_als);
    cudaGetSymbolAddress((void**)&ald,  g_ald);
    cudaGetSymbolAddress((void**)&x3,   g_x3);
    cudaGetSymbolAddress((void**)&pool, g_pool);
    cudaGetSymbolAddress((void**)&cnt,  g_cnt);
    cudaGetSymbolAddress((void**)&deg,  g_deg);
    cudaGetSymbolAddress((void**)&off,  g_off);
    cudaGetSymbolAddress((void**)&cur,  g_cur);
    cudaGetSymbolAddress((void**)&col,  g_col);

    const int* src = ei;
    const int* dst = ei + N_EDGES;

    const int AGG_GRID = (N_NODES * 32 + 255) / 256;

    // ---- CSR build (by destination) ----
    fill_int_kernel<<<(N_NODES + 255) / 256, 256>>>(deg, 0, N_NODES);
    hist_kernel<<<(ETOT + 255) / 256, 256>>>(dst, deg);
    scan_kernel<<<1, 1024>>>(deg, off, cur);
    scatter_kernel<<<(ETOT + 255) / 256, 256>>>(src, dst, cur, col);

    // Layer 1: x1 = elu(gat(x) + b1)
    {
        dim3 grid(D1 / 128, (N_NODES + 127) / 128);
        mma_gemm_kernel<<<grid, 256>>>(x, W1, h, N_NODES, FIN, D1);
        attn_logits_kernel<<<(N_NODES * H1 * 32 + 255) / 256, 256>>>(h, a1s, a1d, als, ald, N_NODES, H1);
        gat_agg_kernel<H1, 1><<<AGG_GRID, 256>>>(off, col, als, ald, h, b1, nullptr, x1);
    }
    // Layer 2: x2 = elu(x1 + gat(x1) + b2)
    {
        dim3 grid(D1 / 128, (N_NODES + 127) / 128);
        mma_gemm_kernel<<<grid, 256>>>(x1, W2, h, N_NODES, D1, D1);
        attn_logits_kernel<<<(N_NODES * H1 * 32 + 255) / 256, 256>>>(h, a2s, a2d, als, ald, N_NODES, H1);
        gat_agg_kernel<H1, 2><<<AGG_GRID, 256>>>(off, col, als, ald, h, b2, x1, x2);
    }
    // Layer 3: x3 = mean-head gat(x2) + b3
    {
        dim3 grid((H3 * HID) / 128, (N_NODES + 127) / 128);
        mma_gemm_kernel<<<grid, 256>>>(x2, W3, h, N_NODES, D1, H3 * HID);
        attn_logits_kernel<<<(N_NODES * H3 * 32 + 255) / 256, 256>>>(h, a3s, a3d, als, ald, N_NODES, H3);
        gat_agg_kernel<H3, 3><<<AGG_GRID, 256>>>(off, col, als, ald, h, b3, nullptr, x3);
    }

    // Global mean pool + head
    fill_kernel<<<(NGRAPH * HID + 255) / 256, 256>>>(pool, 0.f, NGRAPH * HID);
    fill_kernel<<<(NGRAPH + 255) / 256, 256>>>(cnt, 0.f, NGRAPH);
    pool_kernel<<<(N_NODES * HID + 255) / 256, 256>>>(x3, batch, pool, cnt);
    head_kernel<<<1, NGRAPH * NCLS>>>(pool, cnt, Wc, bc, out);
}

// round 12
// speedup vs baseline: 1.4384x; 1.4384x over previous
#include <cuda_runtime.h>
#include <math.h>
#include <stdint.h>

#define N_NODES 10000
#define N_EDGES 160000
#define FIN     256
#define HID     128
#define H1      5
#define H3      3
#define NGRAPH  64
#define NCLS    10
#define D1      (H1*HID)   /* 640 */
#define ETOT    (N_EDGES + N_NODES)

// ---------------- device scratch (no allocation allowed) ----------------
__device__ float g_h  [N_NODES * D1];
__device__ float g_x1 [N_NODES * D1];
__device__ float g_x2 [N_NODES * D1];
__device__ float g_als[N_NODES * H1];
__device__ float g_ald[N_NODES * H1];
__device__ float g_x3 [N_NODES * HID];
__device__ float g_pool[NGRAPH * HID];
__device__ float g_cnt [NGRAPH];
// CSR scratch
__device__ int g_deg[N_NODES];
__device__ int g_off[N_NODES + 1];
__device__ int g_cur[N_NODES];
__device__ int g_col[ETOT];

// ---------------- fills ----------------
__global__ void fill_kernel(float* p, float v, int n) {
    int i = blockIdx.x * blockDim.x + threadIdx.x;
    if (i < n) p[i] = v;
}
__global__ void fill_int_kernel(int* p, int v, int n) {
    int i = blockIdx.x * blockDim.x + threadIdx.x;
    if (i < n) p[i] = v;
}

// ---------------- CSR build: histogram -> scan -> scatter ----------------
__global__ void hist_kernel(const int* __restrict__ dst, int* __restrict__ deg) {
    int i = blockIdx.x * blockDim.x + threadIdx.x;
    if (i >= ETOT) return;
    int d = (i < N_EDGES) ? dst[i] : (i - N_EDGES);
    atomicAdd(&deg[d], 1);
}

__global__ void scan_kernel(const int* __restrict__ deg, int* __restrict__ off,
                            int* __restrict__ cur) {
    __shared__ int part[1024];
    int t = threadIdx.x;
    const int CH = (N_NODES + 1023) / 1024;   // 10
    int base = t * CH;
    int s = 0;
    for (int i = 0; i < CH; i++) {
        int idx = base + i;
        if (idx < N_NODES) s += deg[idx];
    }
    part[t] = s;
    __syncthreads();
    for (int o = 1; o < 1024; o <<= 1) {
        int v = (t >= o) ? part[t - o] : 0;
        __syncthreads();
        part[t] += v;
        __syncthreads();
    }
    int run = (t == 0) ? 0 : part[t - 1];
    for (int i = 0; i < CH; i++) {
        int idx = base + i;
        if (idx < N_NODES) {
            off[idx] = run;
            cur[idx] = run;
            run += deg[idx];
        }
    }
    if (t == 1023) off[N_NODES] = ETOT;
}

__global__ void scatter_kernel(const int* __restrict__ src, const int* __restrict__ dst,
                               int* __restrict__ cur, int* __restrict__ colarr) {
    int i = blockIdx.x * blockDim.x + threadIdx.x;
    if (i >= ETOT) return;
    int d, s;
    if (i < N_EDGES) { s = src[i]; d = dst[i]; } else { s = d = i - N_EDGES; }
    int slot = atomicAdd(&cur[d], 1);
    colarr[slot] = s;
}

// ---------------- tf32 helpers ----------------
__device__ __forceinline__ float to_tf32(float x) {
    uint32_t r;
    asm("cvt.rna.tf32.f32 %0, %1;" : "=r"(r) : "f"(x));
    return __uint_as_float(r);
}

__device__ __forceinline__ void mma_tf32(float* c, const uint32_t* a,
                                         uint32_t b0, uint32_t b1) {
    asm volatile("mma.sync.aligned.m16n8k8.row.col.f32.tf32.tf32.f32 "
        "{%0,%1,%2,%3}, {%4,%5,%6,%7}, {%8,%9}, {%0,%1,%2,%3};"
        : "+f"(c[0]), "+f"(c[1]), "+f"(c[2]), "+f"(c[3])
        : "r"(a[0]), "r"(a[1]), "r"(a[2]), "r"(a[3]), "r"(b0), "r"(b1));
}

// ---------------- tensor-core tf32 GEMM + fused attention logits ----------------
// C[M,Nd] = A[M,K] @ B[K,Nd]; BM=BN=128, BK=16; 8 warps; warp tile 32x64.
// The 128-wide column block aligns with one head (HID=128): the epilogue also
// reduces als/ald for its 128 rows x head = blockIdx.x, eliminating the
// separate attn_logits kernel (a full re-read of h).
// Requires Nd % 128 == 0, K % 16 == 0.
#define SSTR 136   /* smem row stride (floats): conflict-free frag loads */
__global__ void __launch_bounds__(256)
mma_gemm_kernel(const float* __restrict__ A, const float* __restrict__ B,
                float* __restrict__ C, int M, int K, int Nd,
                const float* __restrict__ a_s, const float* __restrict__ a_d,
                float* __restrict__ als, float* __restrict__ ald, int H) {
    __shared__ float As[16][SSTR];   // As[k][m]
    __shared__ float Bs[16][SSTR];   // Bs[k][n]
    __shared__ float sals[128];
    __shared__ float sald[128];
    int tid = threadIdx.x;
    int lane = tid & 31;
    int wid = tid >> 5;
    int wm = (wid & 3) * 32;   // warp row offset within block
    int wn = (wid >> 2) * 64;  // warp col offset within block
    int rowBase = blockIdx.y * 128;
    int colBase = blockIdx.x * 128;
    int head = blockIdx.x;     // Nd/128 == H, colBase/HID == head
    int g = lane >> 2, t4 = lane & 3;

    if (tid < 128) { sals[tid] = 0.f; sald[tid] = 0.f; }

    float c[2][8][4];
    #pragma unroll
    for (int mt = 0; mt < 2; mt++)
        #pragma unroll
        for (int nt = 0; nt < 8; nt++)
            #pragma unroll
            for (int i = 0; i < 4; i++) c[mt][nt][i] = 0.f;

    for (int k0 = 0; k0 < K; k0 += 16) {
        // A tile: 128 rows x 16 k  (store transposed As[k][m])
        #pragma unroll
        for (int it = 0; it < 2; it++) {
            int f = tid + it * 256;        // 0..511 float4 slots
            int row = f >> 2, q = f & 3;
            float4 a4 = make_float4(0.f, 0.f, 0.f, 0.f);
            int grow = rowBase + row;
            if (grow < M) a4 = *(const float4*)&A[(size_t)grow * K + k0 + q * 4];
            As[q * 4 + 0][row] = to_tf32(a4.x);
            As[q * 4 + 1][row] = to_tf32(a4.y);
            As[q * 4 + 2][row] = to_tf32(a4.z);
            As[q * 4 + 3][row] = to_tf32(a4.w);
        }
        // B tile: 16 k x 128 cols
        #pragma unroll
        for (int it = 0; it < 2; it++) {
            int f = tid + it * 256;
            int kr = f >> 5, c4 = (f & 31) * 4;
            float4 b4 = *(const float4*)&B[(size_t)(k0 + kr) * Nd + colBase + c4];
            b4.x = to_tf32(b4.x); b4.y = to_tf32(b4.y);
            b4.z = to_tf32(b4.z); b4.w = to_tf32(b4.w);
            *(float4*)&Bs[kr][c4] = b4;
        }
        __syncthreads();
        #pragma unroll
        for (int kk = 0; kk < 16; kk += 8) {
            uint32_t a[2][4];
            #pragma unroll
            for (int mt = 0; mt < 2; mt++) {
                int r0 = wm + mt * 16 + g;
                a[mt][0] = __float_as_uint(As[kk + t4    ][r0    ]);
                a[mt][1] = __float_as_uint(As[kk + t4    ][r0 + 8]);
                a[mt][2] = __float_as_uint(As[kk + t4 + 4][r0    ]);
                a[mt][3] = __float_as_uint(As[kk + t4 + 4][r0 + 8]);
            }
            #pragma unroll
            for (int nt = 0; nt < 8; nt++) {
                int cn = wn + nt * 8 + g;
                uint32_t b0 = __float_as_uint(Bs[kk + t4    ][cn]);
                uint32_t b1 = __float_as_uint(Bs[kk + t4 + 4][cn]);
                mma_tf32(c[0][nt], a[0], b0, b1);
                mma_tf32(c[1][nt], a[1], b0, b1);
            }
        }
        __syncthreads();
    }

    // ---- epilogue: store C + fused per-row attention logit partials ----
    const float* as_h = a_s + head * HID;
    const float* ad_h = a_d + head * HID;
    float ps[4] = {0.f, 0.f, 0.f, 0.f};   // row slots: [mt*2 + hi]
    float pd[4] = {0.f, 0.f, 0.f, 0.f};
    #pragma unroll
    for (int mt = 0; mt < 2; mt++) {
        int r0 = rowBase + wm + mt * 16 + g;
        #pragma unroll
        for (int nt = 0; nt < 8; nt++) {
            int ccl = wn + nt * 8 + (t4 << 1);    // col within head
            int cc = colBase + ccl;
            float a0 = __ldg(&as_h[ccl]), a1 = __ldg(&as_h[ccl + 1]);
            float d0 = __ldg(&ad_h[ccl]), d1 = __ldg(&ad_h[ccl + 1]);
            if (r0 < M)
                *(float2*)&C[(size_t)r0 * Nd + cc] = make_float2(c[mt][nt][0], c[mt][nt][1]);
            if (r0 + 8 < M)
                *(float2*)&C[(size_t)(r0 + 8) * Nd + cc] = make_float2(c[mt][nt][2], c[mt][nt][3]);
            ps[mt * 2 + 0] += c[mt][nt][0] * a0 + c[mt][nt][1] * a1;
            ps[mt * 2 + 1] += c[mt][nt][2] * a0 + c[mt][nt][3] * a1;
            pd[mt * 2 + 0] += c[mt][nt][0] * d0 + c[mt][nt][1] * d1;
            pd[mt * 2 + 1] += c[mt][nt][2] * d0 + c[mt][nt][3] * d1;
        }
    }
    // reduce over the 4 t4 lanes sharing a row (lane bits 0-1)
    #pragma unroll
    for (int o = 1; o <= 2; o <<= 1) {
        #pragma unroll
        for (int j = 0; j < 4; j++) {
            ps[j] += __shfl_xor_sync(0xffffffffu, ps[j], o);
            pd[j] += __shfl_xor_sync(0xffffffffu, pd[j], o);
        }
    }
    if (t4 == 0) {
        #pragma unroll
        for (int j = 0; j < 4; j++) {
            int r = wm + (j >> 1) * 16 + g + ((j & 1) ? 8 : 0);
            atomicAdd(&sals[r], ps[j]);   // 2 warps (wn=0,64) contribute per row
            atomicAdd(&sald[r], pd[j]);
        }
    }
    __syncthreads();
    if (tid < 128) {
        int grow = rowBase + tid;
        if (grow < M) {
            als[grow * H + head] = sals[tid];
            ald[grow * H + head] = sald[tid];
        }
    }
}

// ---------------- fused CSR softmax aggregation + finalize ----------------
// One warp per node. exp computed once per edge (lane-strided), shfl broadcast
// in the accumulate loop (measured-good R8 structure).
// MODE 1: out = elu(agg + b)                 [D = H*HID]
// MODE 2: out = elu(xres + agg + b)          [D = H*HID]
// MODE 3: out = mean_heads(agg) + b          [D = HID]
template<int H, int MODE>
__global__ void __launch_bounds__(256)
gat_agg_kernel(const int* __restrict__ off, const int* __restrict__ col,
               const float* __restrict__ als, const float* __restrict__ ald,
               const float* __restrict__ h, const float* __restrict__ b,
               const float* __restrict__ xres, float* __restrict__ outbuf) {
    int node = (blockIdx.x * blockDim.x + threadIdx.x) >> 5;
    int lane = threadIdx.x & 31;
    if (node >= N_NODES) return;
    int beg = off[node], end = off[node + 1];

    float4 hacc = make_float4(0.f, 0.f, 0.f, 0.f);   // MODE 3 head-mean accumulator

    #pragma unroll
    for (int hh = 0; hh < H; hh++) {
        float ald_d = __ldg(&ald[node * H + hh]);
        // pass 1: max (lane-strided)
        float mx = -1e30f;
        for (int j = beg + lane; j < end; j += 32) {
            float v = __ldg(&als[col[j] * H + hh]) + ald_d;
            v = v > 0.f ? v : 0.2f * v;
            mx = fmaxf(mx, v);
        }
        #pragma unroll
        for (int o = 16; o > 0; o >>= 1)
            mx = fmaxf(mx, __shfl_xor_sync(0xffffffffu, mx, o));
        // pass 2: chunks of 32 edges; lane computes one exp; shfl broadcast
        float4 acc = make_float4(0.f, 0.f, 0.f, 0.f);
        float ssum = 0.f;
        for (int j0 = beg; j0 < end; j0 += 32) {
            int jj = j0 + lane;
            float ex = 0.f;
            int sc = 0;
            if (jj < end) {
                sc = col[jj];
                float v = __ldg(&als[sc * H + hh]) + ald_d;
                v = v > 0.f ? v : 0.2f * v;
                ex = __expf(v - mx);
            }
            ssum += ex;
            int cnt = end - j0; if (cnt > 32) cnt = 32;
            for (int t = 0; t < cnt; t++) {
                float exb = __shfl_sync(0xffffffffu, ex, t);
                int   sb  = __shfl_sync(0xffffffffu, sc, t);
                float4 hv = ((const float4*)(h + ((size_t)sb * H + hh) * HID))[lane];
                acc.x += exb * hv.x;
                acc.y += exb * hv.y;
                acc.z += exb * hv.z;
                acc.w += exb * hv.w;
            }
        }
        #pragma unroll
        for (int o = 16; o > 0; o >>= 1)
            ssum += __shfl_xor_sync(0xffffffffu, ssum, o);
        float inv = 1.f / (ssum + 1e-16f);
        acc.x *= inv; acc.y *= inv; acc.z *= inv; acc.w *= inv;

        if (MODE == 3) {
            hacc.x += acc.x; hacc.y += acc.y; hacc.z += acc.z; hacc.w += acc.w;
        } else {
            int r = hh * HID + lane * 4;
            float4 bb = *(const float4*)&b[r];
            size_t idx = (size_t)node * (H * HID) + r;
            float4 v4;
            if (MODE == 2) {
                float4 xr = *(const float4*)&xres[idx];
                v4.x = xr.x + acc.x + bb.x;
                v4.y = xr.y + acc.y + bb.y;
                v4.z = xr.z + acc.z + bb.z;
                v4.w = xr.w + acc.w + bb.w;
            } else {
                v4.x = acc.x + bb.x;
                v4.y = acc.y + bb.y;
                v4.z = acc.z + bb.z;
                v4.w = acc.w + bb.w;
            }
            v4.x = v4.x > 0.f ? v4.x : (expf(v4.x) - 1.f);
            v4.y = v4.y > 0.f ? v4.y : (expf(v4.y) - 1.f);
            v4.z = v4.z > 0.f ? v4.z : (expf(v4.z) - 1.f);
            v4.w = v4.w > 0.f ? v4.w : (expf(v4.w) - 1.f);
            *(float4*)&outbuf[idx] = v4;
        }
    }
    if (MODE == 3) {
        int r = lane * 4;
        float4 bb = *(const float4*)&b[r];
        const float s = 1.f / (float)H;
        float4 v4 = make_float4(hacc.x * s + bb.x, hacc.y * s + bb.y,
                                hacc.z * s + bb.z, hacc.w * s + bb.w);
        *(float4*)&outbuf[(size_t)node * HID + r] = v4;
    }
}

// ---------------- global mean pool ----------------
__global__ void pool_kernel(const float* __restrict__ x3, const int* __restrict__ batch,
                            float* __restrict__ pool, float* __restrict__ cnt) {
    int i = blockIdx.x * blockDim.x + threadIdx.x;
    if (i >= N_NODES * HID) return;
    int n = i / HID, c = i % HID;
    int g = batch[n];
    atomicAdd(&pool[(size_t)g * HID + c], x3[i]);
    if (c == 0) atomicAdd(&cnt[g], 1.f);
}

// ---------------- classifier head + log_softmax ----------------
__global__ void head_kernel(const float* __restrict__ pool, const float* __restrict__ cnt,
                            const float* __restrict__ Wc, const float* __restrict__ bc,
                            float* __restrict__ out) {
    __shared__ float sl[NGRAPH][NCLS];
    __shared__ float lse[NGRAPH];
    int tid = threadIdx.x;               // 640 threads
    int g = tid / NCLS, k = tid % NCLS;
    float c = cnt[g]; c = c < 1.f ? 1.f : c;
    float acc = bc[k];
    #pragma unroll 8
    for (int j = 0; j < HID; j++)
        acc += (pool[(size_t)g * HID + j] / c) * Wc[j * NCLS + k];
    sl[g][k] = acc;
    out[g * NCLS + k] = acc;             // logits
    __syncthreads();
    if (k == 0) {
        float mx = sl[g][0];
        #pragma unroll
        for (int j = 1; j < NCLS; j++) mx = fmaxf(mx, sl[g][j]);
        float s = 0.f;
        #pragma unroll
        for (int j = 0; j < NCLS; j++) s += expf(sl[g][j] - mx);
        lse[g] = mx + logf(s);
    }
    __syncthreads();
    out[NGRAPH * NCLS + g * NCLS + k] = sl[g][k] - lse[g];   // log_softmax
}

extern "C" void kernel_launch(void* const* d_in, const int* in_sizes, int n_in,
                              void* d_out, int out_size) {
    const float* x     = (const float*)d_in[0];
    const int*   ei    = (const int*)  d_in[1];
    const int*   batch = (const int*)  d_in[2];
    const float* W1  = (const float*)d_in[3];
    const float* a1s = (const float*)d_in[4];
    const float* a1d = (const float*)d_in[5];
    const float* b1  = (const float*)d_in[6];
    const float* W2  = (const float*)d_in[7];
    const float* a2s = (const float*)d_in[8];
    const float* a2d = (const float*)d_in[9];
    const float* b2  = (const float*)d_in[10];
    const float* W3  = (const float*)d_in[11];
    const float* a3s = (const float*)d_in[12];
    const float* a3d = (const float*)d_in[13];
    const float* b3  = (const float*)d_in[14];
    const float* Wc  = (const float*)d_in[15];
    const float* bc  = (const float*)d_in[16];
    float* out = (float*)d_out;

    float *h, *x1, *x2, *als, *ald, *x3, *pool, *cnt;
    int *deg, *off, *cur, *col;
    cudaGetSymbolAddress((void**)&h,    g_h);
    cudaGetSymbolAddress((void**)&x1,   g_x1);
    cudaGetSymbolAddress((void**)&x2,   g_x2);
    cudaGetSymbolAddress((void**)&als,  g_als);
    cudaGetSymbolAddress((void**)&ald,  g_ald);
    cudaGetSymbolAddress((void**)&x3,   g_x3);
    cudaGetSymbolAddress((void**)&pool, g_pool);
    cudaGetSymbolAddress((void**)&cnt,  g_cnt);
    cudaGetSymbolAddress((void**)&deg,  g_deg);
    cudaGetSymbolAddress((void**)&off,  g_off);
    cudaGetSymbolAddress((void**)&cur,  g_cur);
    cudaGetSymbolAddress((void**)&col,  g_col);

    const int* src = ei;
    const int* dst = ei + N_EDGES;

    const int AGG_GRID = (N_NODES * 32 + 255) / 256;

    // ---- CSR build (by destination) ----
    fill_int_kernel<<<(N_NODES + 255) / 256, 256>>>(deg, 0, N_NODES);
    hist_kernel<<<(ETOT + 255) / 256, 256>>>(dst, deg);
    scan_kernel<<<1, 1024>>>(deg, off, cur);
    scatter_kernel<<<(ETOT + 255) / 256, 256>>>(src, dst, cur, col);

    // Layer 1: x1 = elu(gat(x) + b1)
    {
        dim3 grid(D1 / 128, (N_NODES + 127) / 128);
        mma_gemm_kernel<<<grid, 256>>>(x, W1, h, N_NODES, FIN, D1, a1s, a1d, als, ald, H1);
        gat_agg_kernel<H1, 1><<<AGG_GRID, 256>>>(off, col, als, ald, h, b1, nullptr, x1);
    }
    // Layer 2: x2 = elu(x1 + gat(x1) + b2)
    {
        dim3 grid(D1 / 128, (N_NODES + 127) / 128);
        mma_gemm_kernel<<<grid, 256>>>(x1, W2, h, N_NODES, D1, D1, a2s, a2d, als, ald, H1);
        gat_agg_kernel<H1, 2><<<AGG_GRID, 256>>>(off, col, als, ald, h, b2, x1, x2);
    }
    // Layer 3: x3 = mean-head gat(x2) + b3
    {
        dim3 grid((H3 * HID) / 128, (N_NODES + 127) / 128);
        mma_gemm_kernel<<<grid, 256>>>(x2, W3, h, N_NODES, D1, H3 * HID, a3s, a3d, als, ald, H3);
        gat_agg_kernel<H3, 3><<<AGG_GRID, 256>>>(off, col, als, ald, h, b3, nullptr, x3);
    }

    // Global mean pool + head
    fill_kernel<<<(NGRAPH * HID + 255) / 256, 256>>>(pool, 0.f, NGRAPH * HID);
    fill_kernel<<<(NGRAPH + 255) / 256, 256>>>(cnt, 0.f, NGRAPH);
    pool_kernel<<<(N_NODES * HID + 255) / 256, 256>>>(x3, batch, pool, cnt);
    head_kernel<<<1, NGRAPH * NCLS>>>(pool, cnt, Wc, bc, out);
}

// round 13
// speedup vs baseline: 1.7652x; 1.2272x over previous
#include <cuda_runtime.h>
#include <math.h>
#include <stdint.h>

#define N_NODES 10000
#define N_EDGES 160000
#define FIN     256
#define HID     128
#define H1      5
#define H3      3
#define NGRAPH  64
#define NCLS    10
#define D1      (H1*HID)   /* 640 */
#define ETOT    (N_EDGES + N_NODES)

// ---------------- device scratch (no allocation allowed) ----------------
__device__ float g_h  [N_NODES * D1];
__device__ float g_x1 [N_NODES * D1];
__device__ float g_x2 [N_NODES * D1];
__device__ float g_als[N_NODES * H1];
__device__ float g_ald[N_NODES * H1];
__device__ float g_x3 [N_NODES * HID];
__device__ float g_pool[NGRAPH * HID];
// CSR scratch
__device__ int g_deg[N_NODES];
__device__ int g_off[N_NODES + 1];
__device__ int g_cur[N_NODES];
__device__ int g_col[ETOT];

// ---------------- fills ----------------
__global__ void fill_int_kernel(int* p, int v, int n) {
    int i = blockIdx.x * blockDim.x + threadIdx.x;
    if (i < n) p[i] = v;
}

// ---------------- CSR build: histogram -> scan -> scatter ----------------
__global__ void hist_kernel(const int* __restrict__ dst, int* __restrict__ deg) {
    int i = blockIdx.x * blockDim.x + threadIdx.x;
    if (i >= ETOT) return;
    int d = (i < N_EDGES) ? dst[i] : (i - N_EDGES);
    atomicAdd(&deg[d], 1);
}

__global__ void scan_kernel(const int* __restrict__ deg, int* __restrict__ off,
                            int* __restrict__ cur) {
    __shared__ int part[1024];
    int t = threadIdx.x;
    const int CH = (N_NODES + 1023) / 1024;   // 10
    int base = t * CH;
    int s = 0;
    for (int i = 0; i < CH; i++) {
        int idx = base + i;
        if (idx < N_NODES) s += deg[idx];
    }
    part[t] = s;
    __syncthreads();
    for (int o = 1; o < 1024; o <<= 1) {
        int v = (t >= o) ? part[t - o] : 0;
        __syncthreads();
        part[t] += v;
        __syncthreads();
    }
    int run = (t == 0) ? 0 : part[t - 1];
    for (int i = 0; i < CH; i++) {
        int idx = base + i;
        if (idx < N_NODES) {
            off[idx] = run;
            cur[idx] = run;
            run += deg[idx];
        }
    }
    if (t == 1023) off[N_NODES] = ETOT;
}

__global__ void scatter_kernel(const int* __restrict__ src, const int* __restrict__ dst,
                               int* __restrict__ cur, int* __restrict__ colarr) {
    int i = blockIdx.x * blockDim.x + threadIdx.x;
    if (i >= ETOT) return;
    int d, s;
    if (i < N_EDGES) { s = src[i]; d = dst[i]; } else { s = d = i - N_EDGES; }
    int slot = atomicAdd(&cur[d], 1);
    colarr[slot] = s;
}

// ---------------- tf32 / cp.async helpers ----------------
__device__ __forceinline__ float to_tf32(float x) {
    uint32_t r;
    asm("cvt.rna.tf32.f32 %0, %1;" : "=r"(r) : "f"(x));
    return __uint_as_float(r);
}
__device__ __forceinline__ uint32_t f2t(float x) {
    uint32_t r;
    asm("cvt.rna.tf32.f32 %0, %1;" : "=r"(r) : "f"(x));
    return r;
}

__device__ __forceinline__ void mma_tf32(float* c, const uint32_t* a,
                                         uint32_t b0, uint32_t b1) {
    asm volatile("mma.sync.aligned.m16n8k8.row.col.f32.tf32.tf32.f32 "
        "{%0,%1,%2,%3}, {%4,%5,%6,%7}, {%8,%9}, {%0,%1,%2,%3};"
        : "+f"(c[0]), "+f"(c[1]), "+f"(c[2]), "+f"(c[3])
        : "r"(a[0]), "r"(a[1]), "r"(a[2]), "r"(a[3]), "r"(b0), "r"(b1));
}

__device__ __forceinline__ void cp_async16(void* smem, const void* gmem, bool valid) {
    uint32_t s = (uint32_t)__cvta_generic_to_shared(smem);
    int sz = valid ? 16 : 0;
    asm volatile("cp.async.cg.shared.global [%0], [%1], 16, %2;"
                 :: "r"(s), "l"(gmem), "r"(sz));
}
__device__ __forceinline__ void cp_commit() {
    asm volatile("cp.async.commit_group;");
}
template<int Nw> __device__ __forceinline__ void cp_wait() {
    asm volatile("cp.async.wait_group %0;" :: "n"(Nw));
}

// ---------------- tensor-core tf32 GEMM (cp.async 2-stage) + fused logits ----
// C[M,Nd] = A[M,K] @ B[K,Nd]; BM=BN=128, BK=16; 8 warps; warp tile 32x64.
// A smem: [row][k] stride 20 (conflict-free, 16B pad); B smem: [k][col] stride 136.
// cvt to tf32 at fragment read (ALU pipe, overlapped with tensor pipe).
// Epilogue fuses per-row attention logits for head = blockIdx.x (Nd/128 == H).
#define ASTR 20
#define BSTR 136
__global__ void __launch_bounds__(256)
mma_gemm_kernel(const float* __restrict__ A, const float* __restrict__ B,
                float* __restrict__ C, int M, int K, int Nd,
                const float* __restrict__ a_s, const float* __restrict__ a_d,
                float* __restrict__ als, float* __restrict__ ald, int H) {
    __shared__ float As[2][128 * ASTR];   // [buf][row*ASTR + k]
    __shared__ float Bs[2][16 * BSTR];    // [buf][k*BSTR + col]
    __shared__ float sals[128];
    __shared__ float sald[128];
    int tid = threadIdx.x;
    int lane = tid & 31;
    int wid = tid >> 5;
    int wm = (wid & 3) * 32;
    int wn = (wid >> 2) * 64;
    int rowBase = blockIdx.y * 128;
    int colBase = blockIdx.x * 128;
    int head = blockIdx.x;
    int g = lane >> 2, t4 = lane & 3;

    if (tid < 128) { sals[tid] = 0.f; sald[tid] = 0.f; }

    float c[2][8][4];
    #pragma unroll
    for (int mt = 0; mt < 2; mt++)
        #pragma unroll
        for (int nt = 0; nt < 8; nt++)
            #pragma unroll
            for (int i = 0; i < 4; i++) c[mt][nt][i] = 0.f;

    // per-thread copy slots: 2 chunks of A (128x16), 2 chunks of B (16x128)
    int arow0 = tid >> 2, aq0 = (tid & 3) * 4;           // it=0
    int arow1 = (tid + 256) >> 2, aq1 = ((tid + 256) & 3) * 4;
    int bkr0 = tid >> 5, bc0 = (tid & 31) * 4;
    int bkr1 = (tid + 256) >> 5, bc1 = ((tid + 256) & 31) * 4;

    auto issue = [&](int buf, int k0) {
        cp_async16(&As[buf][arow0 * ASTR + aq0],
                   &A[(size_t)(rowBase + arow0) * K + k0 + aq0], rowBase + arow0 < M);
        cp_async16(&As[buf][arow1 * ASTR + aq1],
                   &A[(size_t)(rowBase + arow1) * K + k0 + aq1], rowBase + arow1 < M);
        cp_async16(&Bs[buf][bkr0 * BSTR + bc0],
                   &B[(size_t)(k0 + bkr0) * Nd + colBase + bc0], true);
        cp_async16(&Bs[buf][bkr1 * BSTR + bc1],
                   &B[(size_t)(k0 + bkr1) * Nd + colBase + bc1], true);
        cp_commit();
    };

    issue(0, 0);
    int buf = 0;
    for (int k0 = 0; k0 < K; k0 += 16) {
        bool more = (k0 + 16) < K;
        if (more) { issue(buf ^ 1, k0 + 16); cp_wait<1>(); }
        else      { cp_wait<0>(); }
        __syncthreads();
        #pragma unroll
        for (int kk = 0; kk < 16; kk += 8) {
            uint32_t a[2][4];
            #pragma unroll
            for (int mt = 0; mt < 2; mt++) {
                int r0 = wm + mt * 16 + g;
                a[mt][0] = f2t(As[buf][ r0      * ASTR + kk + t4    ]);
                a[mt][1] = f2t(As[buf][(r0 + 8) * ASTR + kk + t4    ]);
                a[mt][2] = f2t(As[buf][ r0      * ASTR + kk + t4 + 4]);
                a[mt][3] = f2t(As[buf][(r0 + 8) * ASTR + kk + t4 + 4]);
            }
            #pragma unroll
            for (int nt = 0; nt < 8; nt++) {
                int cn = wn + nt * 8 + g;
                uint32_t b0 = f2t(Bs[buf][(kk + t4    ) * BSTR + cn]);
                uint32_t b1 = f2t(Bs[buf][(kk + t4 + 4) * BSTR + cn]);
                mma_tf32(c[0][nt], a[0], b0, b1);
                mma_tf32(c[1][nt], a[1], b0, b1);
            }
        }
        __syncthreads();
        buf ^= 1;
    }

    // ---- epilogue: store C + fused per-row attention logit partials ----
    const float* as_h = a_s + head * HID;
    const float* ad_h = a_d + head * HID;
    float ps[4] = {0.f, 0.f, 0.f, 0.f};
    float pd[4] = {0.f, 0.f, 0.f, 0.f};
    #pragma unroll
    for (int mt = 0; mt < 2; mt++) {
        int r0 = rowBase + wm + mt * 16 + g;
        #pragma unroll
        for (int nt = 0; nt < 8; nt++) {
            int ccl = wn + nt * 8 + (t4 << 1);
            int cc = colBase + ccl;
            float a0 = __ldg(&as_h[ccl]), a1 = __ldg(&as_h[ccl + 1]);
            float d0 = __ldg(&ad_h[ccl]), d1 = __ldg(&ad_h[ccl + 1]);
            if (r0 < M)
                *(float2*)&C[(size_t)r0 * Nd + cc] = make_float2(c[mt][nt][0], c[mt][nt][1]);
            if (r0 + 8 < M)
                *(float2*)&C[(size_t)(r0 + 8) * Nd + cc] = make_float2(c[mt][nt][2], c[mt][nt][3]);
            ps[mt * 2 + 0] += c[mt][nt][0] * a0 + c[mt][nt][1] * a1;
            ps[mt * 2 + 1] += c[mt][nt][2] * a0 + c[mt][nt][3] * a1;
            pd[mt * 2 + 0] += c[mt][nt][0] * d0 + c[mt][nt][1] * d1;
            pd[mt * 2 + 1] += c[mt][nt][2] * d0 + c[mt][nt][3] * d1;
        }
    }
    #pragma unroll
    for (int o = 1; o <= 2; o <<= 1) {
        #pragma unroll
        for (int j = 0; j < 4; j++) {
            ps[j] += __shfl_xor_sync(0xffffffffu, ps[j], o);
            pd[j] += __shfl_xor_sync(0xffffffffu, pd[j], o);
        }
    }
    if (t4 == 0) {
        #pragma unroll
        for (int j = 0; j < 4; j++) {
            int r = wm + (j >> 1) * 16 + g + ((j & 1) ? 8 : 0);
            atomicAdd(&sals[r], ps[j]);
            atomicAdd(&sald[r], pd[j]);
        }
    }
    __syncthreads();
    if (tid < 128) {
        int grow = rowBase + tid;
        if (grow < M) {
            als[grow * H + head] = sals[tid];
            ald[grow * H + head] = sald[tid];
        }
    }
}

// ---------------- fused CSR softmax aggregation + finalize ----------------
// MODE 1: out = elu(agg + b); MODE 2: out = elu(xres + agg + b);
// MODE 3: out = mean_heads(agg) + b
template<int H, int MODE>
__global__ void __launch_bounds__(256)
gat_agg_kernel(const int* __restrict__ off, const int* __restrict__ col,
               const float* __restrict__ als, const float* __restrict__ ald,
               const float* __restrict__ h, const float* __restrict__ b,
               const float* __restrict__ xres, float* __restrict__ outbuf) {
    int node = (blockIdx.x * blockDim.x + threadIdx.x) >> 5;
    int lane = threadIdx.x & 31;
    if (node >= N_NODES) return;
    int beg = off[node], end = off[node + 1];

    float4 hacc = make_float4(0.f, 0.f, 0.f, 0.f);

    #pragma unroll
    for (int hh = 0; hh < H; hh++) {
        float ald_d = __ldg(&ald[node * H + hh]);
        float mx = -1e30f;
        for (int j = beg + lane; j < end; j += 32) {
            float v = __ldg(&als[col[j] * H + hh]) + ald_d;
            v = v > 0.f ? v : 0.2f * v;
            mx = fmaxf(mx, v);
        }
        #pragma unroll
        for (int o = 16; o > 0; o >>= 1)
            mx = fmaxf(mx, __shfl_xor_sync(0xffffffffu, mx, o));
        float4 acc = make_float4(0.f, 0.f, 0.f, 0.f);
        float ssum = 0.f;
        for (int j0 = beg; j0 < end; j0 += 32) {
            int jj = j0 + lane;
            float ex = 0.f;
            int sc = 0;
            if (jj < end) {
                sc = col[jj];
                float v = __ldg(&als[sc * H + hh]) + ald_d;
                v = v > 0.f ? v : 0.2f * v;
                ex = __expf(v - mx);
            }
            ssum += ex;
            int cnt = end - j0; if (cnt > 32) cnt = 32;
            for (int t = 0; t < cnt; t++) {
                float exb = __shfl_sync(0xffffffffu, ex, t);
                int   sb  = __shfl_sync(0xffffffffu, sc, t);
                float4 hv = ((const float4*)(h + ((size_t)sb * H + hh) * HID))[lane];
                acc.x += exb * hv.x;
                acc.y += exb * hv.y;
                acc.z += exb * hv.z;
                acc.w += exb * hv.w;
            }
        }
        #pragma unroll
        for (int o = 16; o > 0; o >>= 1)
            ssum += __shfl_xor_sync(0xffffffffu, ssum, o);
        float inv = 1.f / (ssum + 1e-16f);
        acc.x *= inv; acc.y *= inv; acc.z *= inv; acc.w *= inv;

        if (MODE == 3) {
            hacc.x += acc.x; hacc.y += acc.y; hacc.z += acc.z; hacc.w += acc.w;
        } else {
            int r = hh * HID + lane * 4;
            float4 bb = *(const float4*)&b[r];
            size_t idx = (size_t)node * (H * HID) + r;
            float4 v4;
            if (MODE == 2) {
                float4 xr = *(const float4*)&xres[idx];
                v4.x = xr.x + acc.x + bb.x;
                v4.y = xr.y + acc.y + bb.y;
                v4.z = xr.z + acc.z + bb.z;
                v4.w = xr.w + acc.w + bb.w;
            } else {
                v4.x = acc.x + bb.x;
                v4.y = acc.y + bb.y;
                v4.z = acc.z + bb.z;
                v4.w = acc.w + bb.w;
            }
            v4.x = v4.x > 0.f ? v4.x : (expf(v4.x) - 1.f);
            v4.y = v4.y > 0.f ? v4.y : (expf(v4.y) - 1.f);
            v4.z = v4.z > 0.f ? v4.z : (expf(v4.z) - 1.f);
            v4.w = v4.w > 0.f ? v4.w : (expf(v4.w) - 1.f);
            *(float4*)&outbuf[idx] = v4;
        }
    }
    if (MODE == 3) {
        int r = lane * 4;
        float4 bb = *(const float4*)&b[r];
        const float s = 1.f / (float)H;
        float4 v4 = make_float4(hacc.x * s + bb.x, hacc.y * s + bb.y,
                                hacc.z * s + bb.z, hacc.w * s + bb.w);
        *(float4*)&outbuf[(size_t)node * HID + r] = v4;
    }
}

// ---------------- segment mean pool (batch is sorted) ----------------
// one block per graph; binary-search node range; no atomics, no fills
__global__ void pool_seg_kernel(const float* __restrict__ x3, const int* __restrict__ batch,
                                float* __restrict__ pool) {
    __shared__ int sbeg, send;
    int gph = blockIdx.x;
    int c = threadIdx.x;   // 128
    if (c == 0) {
        int lo = 0, hi = N_NODES;
        while (lo < hi) { int mid = (lo + hi) >> 1; if (batch[mid] < gph) lo = mid + 1; else hi = mid; }
        sbeg = lo;
        lo = 0; hi = N_NODES;
        while (lo < hi) { int mid = (lo + hi) >> 1; if (batch[mid] < gph + 1) lo = mid + 1; else hi = mid; }
        send = lo;
    }
    __syncthreads();
    float s = 0.f;
    for (int n = sbeg; n < send; n++) s += x3[(size_t)n * HID + c];
    float cf = (float)(send - sbeg); if (cf < 1.f) cf = 1.f;
    pool[gph * HID + c] = s / cf;
}

// ---------------- classifier head + log_softmax (pool already mean) ------
__global__ void head_kernel(const float* __restrict__ pool,
                            const float* __restrict__ Wc, const float* __restrict__ bc,
                            float* __restrict__ out) {
    __shared__ float sl[NGRAPH][NCLS];
    __shared__ float lse[NGRAPH];
    int tid = threadIdx.x;               // 640 threads
    int g = tid / NCLS, k = tid % NCLS;
    float acc = bc[k];
    #pragma unroll 8
    for (int j = 0; j < HID; j++)
        acc += pool[(size_t)g * HID + j] * Wc[j * NCLS + k];
    sl[g][k] = acc;
    out[g * NCLS + k] = acc;             // logits
    __syncthreads();
    if (k == 0) {
        float mx = sl[g][0];
        #pragma unroll
        for (int j = 1; j < NCLS; j++) mx = fmaxf(mx, sl[g][j]);
        float s = 0.f;
        #pragma unroll
        for (int j = 0; j < NCLS; j++) s += expf(sl[g][j] - mx);
        lse[g] = mx + logf(s);
    }
    __syncthreads();
    out[NGRAPH * NCLS + g * NCLS + k] = sl[g][k] - lse[g];   // log_softmax
}

extern "C" void kernel_launch(void* const* d_in, const int* in_sizes, int n_in,
                              void* d_out, int out_size) {
    const float* x     = (const float*)d_in[0];
    const int*   ei    = (const int*)  d_in[1];
    const int*   batch = (const int*)  d_in[2];
    const float* W1  = (const float*)d_in[3];
    const float* a1s = (const float*)d_in[4];
    const float* a1d = (const float*)d_in[5];
    const float* b1  = (const float*)d_in[6];
    const float* W2  = (const float*)d_in[7];
    const float* a2s = (const float*)d_in[8];
    const float* a2d = (const float*)d_in[9];
    const float* b2  = (const float*)d_in[10];
    const float* W3  = (const float*)d_in[11];
    const float* a3s = (const float*)d_in[12];
    const float* a3d = (const float*)d_in[13];
    const float* b3  = (const float*)d_in[14];
    const float* Wc  = (const float*)d_in[15];
    const float* bc  = (const float*)d_in[16];
    float* out = (float*)d_out;

    float *h, *x1, *x2, *als, *ald, *x3, *pool;
    int *deg, *off, *cur, *col;
    cudaGetSymbolAddress((void**)&h,    g_h);
    cudaGetSymbolAddress((void**)&x1,   g_x1);
    cudaGetSymbolAddress((void**)&x2,   g_x2);
    cudaGetSymbolAddress((void**)&als,  g_als);
    cudaGetSymbolAddress((void**)&ald,  g_ald);
    cudaGetSymbolAddress((void**)&x3,   g_x3);
    cudaGetSymbolAddress((void**)&pool, g_pool);
    cudaGetSymbolAddress((void**)&deg,  g_deg);
    cudaGetSymbolAddress((void**)&off,  g_off);
    cudaGetSymbolAddress((void**)&cur,  g_cur);
    cudaGetSymbolAddress((void**)&col,  g_col);

    const int* src = ei;
    const int* dst = ei + N_EDGES;

    const int AGG_GRID = (N_NODES * 32 + 255) / 256;

    // ---- CSR build (by destination) ----
    fill_int_kernel<<<(N_NODES + 255) / 256, 256>>>(deg, 0, N_NODES);
    hist_kernel<<<(ETOT + 255) / 256, 256>>>(dst, deg);
    scan_kernel<<<1, 1024>>>(deg, off, cur);
    scatter_kernel<<<(ETOT + 255) / 256, 256>>>(src, dst, cur, col);

    // Layer 1: x1 = elu(gat(x) + b1)
    {
        dim3 grid(D1 / 128, (N_NODES + 127) / 128);
        mma_gemm_kernel<<<grid, 256>>>(x, W1, h, N_NODES, FIN, D1, a1s, a1d, als, ald, H1);
        gat_agg_kernel<H1, 1><<<AGG_GRID, 256>>>(off, col, als, ald, h, b1, nullptr, x1);
    }
    // Layer 2: x2 = elu(x1 + gat(x1) + b2)
    {
        dim3 grid(D1 / 128, (N_NODES + 127) / 128);
        mma_gemm_kernel<<<grid, 256>>>(x1, W2, h, N_NODES, D1, D1, a2s, a2d, als, ald, H1);
        gat_agg_kernel<H1, 2><<<AGG_GRID, 256>>>(off, col, als, ald, h, b2, x1, x2);
    }
    // Layer 3: x3 = mean-head gat(x2) + b3
    {
        dim3 grid((H3 * HID) / 128, (N_NODES + 127) / 128);
        mma_gemm_kernel<<<grid, 256>>>(x2, W3, h, N_NODES, D1, H3 * HID, a3s, a3d, als, ald, H3);
        gat_agg_kernel<H3, 3><<<AGG_GRID, 256>>>(off, col, als, ald, h, b3, nullptr, x3);
    }

    // Segment mean pool + head
    pool_seg_kernel<<<NGRAPH, HID>>>(x3, batch, pool);
    head_kernel<<<1, NGRAPH * NCLS>>>(pool, Wc, bc, out);
}

// round 14
// speedup vs baseline: 1.9024x; 1.0777x over previous
#include <cuda_runtime.h>
#include <math.h>
#include <stdint.h>

#define N_NODES 10000
#define N_EDGES 160000
#define FIN     256
#define HID     128
#define H1      5
#define H3      3
#define NGRAPH  64
#define NCLS    10
#define D1      (H1*HID)   /* 640 */
#define ETOT    (N_EDGES + N_NODES)

// ---------------- device scratch (no allocation allowed) ----------------
__device__ float g_h  [N_NODES * D1];
__device__ float g_x1 [N_NODES * D1];
__device__ float g_x2 [N_NODES * D1];
__device__ float g_als[N_NODES * H1];
__device__ float g_ald[N_NODES * H1];
__device__ float g_x3 [N_NODES * HID];
__device__ float g_pool[NGRAPH * HID];
// CSR scratch
__device__ int g_deg[N_NODES];
__device__ int g_off[N_NODES + 1];
__device__ int g_cur[N_NODES];
__device__ int g_col[ETOT];

// ---------------- fills ----------------
__global__ void fill_int_kernel(int* p, int v, int n) {
    int i = blockIdx.x * blockDim.x + threadIdx.x;
    if (i < n) p[i] = v;
}

// ---------------- CSR build: histogram -> scan -> scatter ----------------
__global__ void hist_kernel(const int* __restrict__ dst, int* __restrict__ deg) {
    int i = blockIdx.x * blockDim.x + threadIdx.x;
    if (i >= ETOT) return;
    int d = (i < N_EDGES) ? dst[i] : (i - N_EDGES);
    atomicAdd(&deg[d], 1);
}

__global__ void scan_kernel(const int* __restrict__ deg, int* __restrict__ off,
                            int* __restrict__ cur) {
    __shared__ int part[1024];
    int t = threadIdx.x;
    const int CH = (N_NODES + 1023) / 1024;   // 10
    int base = t * CH;
    int s = 0;
    for (int i = 0; i < CH; i++) {
        int idx = base + i;
        if (idx < N_NODES) s += deg[idx];
    }
    part[t] = s;
    __syncthreads();
    for (int o = 1; o < 1024; o <<= 1) {
        int v = (t >= o) ? part[t - o] : 0;
        __syncthreads();
        part[t] += v;
        __syncthreads();
    }
    int run = (t == 0) ? 0 : part[t - 1];
    for (int i = 0; i < CH; i++) {
        int idx = base + i;
        if (idx < N_NODES) {
            off[idx] = run;
            cur[idx] = run;
            run += deg[idx];
        }
    }
    if (t == 1023) off[N_NODES] = ETOT;
}

__global__ void scatter_kernel(const int* __restrict__ src, const int* __restrict__ dst,
                               int* __restrict__ cur, int* __restrict__ colarr) {
    int i = blockIdx.x * blockDim.x + threadIdx.x;
    if (i >= ETOT) return;
    int d, s;
    if (i < N_EDGES) { s = src[i]; d = dst[i]; } else { s = d = i - N_EDGES; }
    int slot = atomicAdd(&cur[d], 1);
    colarr[slot] = s;
}

// ---------------- tf32 / cp.async helpers ----------------
__device__ __forceinline__ uint32_t f2t(float x) {
    uint32_t r;
    asm("cvt.rna.tf32.f32 %0, %1;" : "=r"(r) : "f"(x));
    return r;
}

__device__ __forceinline__ void mma_tf32(float* c, const uint32_t* a,
                                         uint32_t b0, uint32_t b1) {
    asm volatile("mma.sync.aligned.m16n8k8.row.col.f32.tf32.tf32.f32 "
        "{%0,%1,%2,%3}, {%4,%5,%6,%7}, {%8,%9}, {%0,%1,%2,%3};"
        : "+f"(c[0]), "+f"(c[1]), "+f"(c[2]), "+f"(c[3])
        : "r"(a[0]), "r"(a[1]), "r"(a[2]), "r"(a[3]), "r"(b0), "r"(b1));
}

__device__ __forceinline__ void cp_async16(void* smem, const void* gmem, bool valid) {
    uint32_t s = (uint32_t)__cvta_generic_to_shared(smem);
    int sz = valid ? 16 : 0;
    asm volatile("cp.async.cg.shared.global [%0], [%1], 16, %2;"
                 :: "r"(s), "l"(gmem), "r"(sz));
}
__device__ __forceinline__ void cp_commit() {
    asm volatile("cp.async.commit_group;");
}
template<int Nw> __device__ __forceinline__ void cp_wait() {
    asm volatile("cp.async.wait_group %0;" :: "n"(Nw));
}

// ---------------- tensor-core tf32 GEMM (cp.async 2-stage) + fused logits ----
// (byte-identical to the measured-good R13 version)
#define ASTR 20
#define BSTR 136
__global__ void __launch_bounds__(256)
mma_gemm_kernel(const float* __restrict__ A, const float* __restrict__ B,
                float* __restrict__ C, int M, int K, int Nd,
                const float* __restrict__ a_s, const float* __restrict__ a_d,
                float* __restrict__ als, float* __restrict__ ald, int H) {
    __shared__ float As[2][128 * ASTR];   // [buf][row*ASTR + k]
    __shared__ float Bs[2][16 * BSTR];    // [buf][k*BSTR + col]
    __shared__ float sals[128];
    __shared__ float sald[128];
    int tid = threadIdx.x;
    int lane = tid & 31;
    int wid = tid >> 5;
    int wm = (wid & 3) * 32;
    int wn = (wid >> 2) * 64;
    int rowBase = blockIdx.y * 128;
    int colBase = blockIdx.x * 128;
    int head = blockIdx.x;
    int g = lane >> 2, t4 = lane & 3;

    if (tid < 128) { sals[tid] = 0.f; sald[tid] = 0.f; }

    float c[2][8][4];
    #pragma unroll
    for (int mt = 0; mt < 2; mt++)
        #pragma unroll
        for (int nt = 0; nt < 8; nt++)
            #pragma unroll
            for (int i = 0; i < 4; i++) c[mt][nt][i] = 0.f;

    int arow0 = tid >> 2, aq0 = (tid & 3) * 4;
    int arow1 = (tid + 256) >> 2, aq1 = ((tid + 256) & 3) * 4;
    int bkr0 = tid >> 5, bc0 = (tid & 31) * 4;
    int bkr1 = (tid + 256) >> 5, bc1 = ((tid + 256) & 31) * 4;

    auto issue = [&](int buf, int k0) {
        cp_async16(&As[buf][arow0 * ASTR + aq0],
                   &A[(size_t)(rowBase + arow0) * K + k0 + aq0], rowBase + arow0 < M);
        cp_async16(&As[buf][arow1 * ASTR + aq1],
                   &A[(size_t)(rowBase + arow1) * K + k0 + aq1], rowBase + arow1 < M);
        cp_async16(&Bs[buf][bkr0 * BSTR + bc0],
                   &B[(size_t)(k0 + bkr0) * Nd + colBase + bc0], true);
        cp_async16(&Bs[buf][bkr1 * BSTR + bc1],
                   &B[(size_t)(k0 + bkr1) * Nd + colBase + bc1], true);
        cp_commit();
    };

    issue(0, 0);
    int buf = 0;
    for (int k0 = 0; k0 < K; k0 += 16) {
        bool more = (k0 + 16) < K;
        if (more) { issue(buf ^ 1, k0 + 16); cp_wait<1>(); }
        else      { cp_wait<0>(); }
        __syncthreads();
        #pragma unroll
        for (int kk = 0; kk < 16; kk += 8) {
            uint32_t a[2][4];
            #pragma unroll
            for (int mt = 0; mt < 2; mt++) {
                int r0 = wm + mt * 16 + g;
                a[mt][0] = f2t(As[buf][ r0      * ASTR + kk + t4    ]);
                a[mt][1] = f2t(As[buf][(r0 + 8) * ASTR + kk + t4    ]);
                a[mt][2] = f2t(As[buf][ r0      * ASTR + kk + t4 + 4]);
                a[mt][3] = f2t(As[buf][(r0 + 8) * ASTR + kk + t4 + 4]);
            }
            #pragma unroll
            for (int nt = 0; nt < 8; nt++) {
                int cn = wn + nt * 8 + g;
                uint32_t b0 = f2t(Bs[buf][(kk + t4    ) * BSTR + cn]);
                uint32_t b1 = f2t(Bs[buf][(kk + t4 + 4) * BSTR + cn]);
                mma_tf32(c[0][nt], a[0], b0, b1);
                mma_tf32(c[1][nt], a[1], b0, b1);
            }
        }
        __syncthreads();
        buf ^= 1;
    }

    const float* as_h = a_s + head * HID;
    const float* ad_h = a_d + head * HID;
    float ps[4] = {0.f, 0.f, 0.f, 0.f};
    float pd[4] = {0.f, 0.f, 0.f, 0.f};
    #pragma unroll
    for (int mt = 0; mt < 2; mt++) {
        int r0 = rowBase + wm + mt * 16 + g;
        #pragma unroll
        for (int nt = 0; nt < 8; nt++) {
            int ccl = wn + nt * 8 + (t4 << 1);
            int cc = colBase + ccl;
            float a0 = __ldg(&as_h[ccl]), a1 = __ldg(&as_h[ccl + 1]);
            float d0 = __ldg(&ad_h[ccl]), d1 = __ldg(&ad_h[ccl + 1]);
            if (r0 < M)
                *(float2*)&C[(size_t)r0 * Nd + cc] = make_float2(c[mt][nt][0], c[mt][nt][1]);
            if (r0 + 8 < M)
                *(float2*)&C[(size_t)(r0 + 8) * Nd + cc] = make_float2(c[mt][nt][2], c[mt][nt][3]);
            ps[mt * 2 + 0] += c[mt][nt][0] * a0 + c[mt][nt][1] * a1;
            ps[mt * 2 + 1] += c[mt][nt][2] * a0 + c[mt][nt][3] * a1;
            pd[mt * 2 + 0] += c[mt][nt][0] * d0 + c[mt][nt][1] * d1;
            pd[mt * 2 + 1] += c[mt][nt][2] * d0 + c[mt][nt][3] * d1;
        }
    }
    #pragma unroll
    for (int o = 1; o <= 2; o <<= 1) {
        #pragma unroll
        for (int j = 0; j < 4; j++) {
            ps[j] += __shfl_xor_sync(0xffffffffu, ps[j], o);
            pd[j] += __shfl_xor_sync(0xffffffffu, pd[j], o);
        }
    }
    if (t4 == 0) {
        #pragma unroll
        for (int j = 0; j < 4; j++) {
            int r = wm + (j >> 1) * 16 + g + ((j & 1) ? 8 : 0);
            atomicAdd(&sals[r], ps[j]);
            atomicAdd(&sald[r], pd[j]);
        }
    }
    __syncthreads();
    if (tid < 128) {
        int grow = rowBase + tid;
        if (grow < M) {
            als[grow * H + head] = sals[tid];
            ald[grow * H + head] = sald[tid];
        }
    }
}

// ---------------- fused CSR softmax aggregation + finalize ----------------
// MODE 1/2: ONE WARP PER (node, head) — 5x parallelism vs per-node loop.
//   MODE 1: out[n,h,:] = elu(agg + b);  MODE 2: out = elu(xres + agg + b)
// MODE 3 (head-mean, H small): one warp per node, loops heads.
template<int H, int MODE>
__global__ void __launch_bounds__(256)
gat_agg_kernel(const int* __restrict__ off, const int* __restrict__ col,
               const float* __restrict__ als, const float* __restrict__ ald,
               const float* __restrict__ h, const float* __restrict__ b,
               const float* __restrict__ xres, float* __restrict__ outbuf) {
    int w = (blockIdx.x * blockDim.x + threadIdx.x) >> 5;
    int lane = threadIdx.x & 31;

    if (MODE != 3) {
        // ---- (node, head) decomposition ----
        if (w >= N_NODES * H) return;
        int node = w / H, hh = w - node * H;
        int beg = off[node], end = off[node + 1];
        float ald_d = __ldg(&ald[node * H + hh]);

        float mx = -1e30f;
        for (int j = beg + lane; j < end; j += 32) {
            float v = __ldg(&als[col[j] * H + hh]) + ald_d;
            v = v > 0.f ? v : 0.2f * v;
            mx = fmaxf(mx, v);
        }
        #pragma unroll
        for (int o = 16; o > 0; o >>= 1)
            mx = fmaxf(mx, __shfl_xor_sync(0xffffffffu, mx, o));

        float4 acc = make_float4(0.f, 0.f, 0.f, 0.f);
        float ssum = 0.f;
        for (int j0 = beg; j0 < end; j0 += 32) {
            int jj = j0 + lane;
            float ex = 0.f;
            int sc = 0;
            if (jj < end) {
                sc = col[jj];
                float v = __ldg(&als[sc * H + hh]) + ald_d;
                v = v > 0.f ? v : 0.2f * v;
                ex = __expf(v - mx);
            }
            ssum += ex;
            int cnt = end - j0; if (cnt > 32) cnt = 32;
            for (int t = 0; t < cnt; t++) {
                float exb = __shfl_sync(0xffffffffu, ex, t);
                int   sb  = __shfl_sync(0xffffffffu, sc, t);
                float4 hv = ((const float4*)(h + ((size_t)sb * H + hh) * HID))[lane];
                acc.x += exb * hv.x;
                acc.y += exb * hv.y;
                acc.z += exb * hv.z;
                acc.w += exb * hv.w;
            }
        }
        #pragma unroll
        for (int o = 16; o > 0; o >>= 1)
            ssum += __shfl_xor_sync(0xffffffffu, ssum, o);
        float inv = 1.f / (ssum + 1e-16f);
        acc.x *= inv; acc.y *= inv; acc.z *= inv; acc.w *= inv;

        int r = hh * HID + lane * 4;
        float4 bb = *(const float4*)&b[r];
        size_t idx = (size_t)node * (H * HID) + r;
        float4 v4;
        if (MODE == 2) {
            float4 xr = *(const float4*)&xres[idx];
            v4.x = xr.x + acc.x + bb.x;
            v4.y = xr.y + acc.y + bb.y;
            v4.z = xr.z + acc.z + bb.z;
            v4.w = xr.w + acc.w + bb.w;
        } else {
            v4.x = acc.x + bb.x;
            v4.y = acc.y + bb.y;
            v4.z = acc.z + bb.z;
            v4.w = acc.w + bb.w;
        }
        v4.x = v4.x > 0.f ? v4.x : (expf(v4.x) - 1.f);
        v4.y = v4.y > 0.f ? v4.y : (expf(v4.y) - 1.f);
        v4.z = v4.z > 0.f ? v4.z : (expf(v4.z) - 1.f);
        v4.w = v4.w > 0.f ? v4.w : (expf(v4.w) - 1.f);
        *(float4*)&outbuf[idx] = v4;
    } else {
        // ---- per-node, loop heads; head-mean output ----
        int node = w;
        if (node >= N_NODES) return;
        int beg = off[node], end = off[node + 1];
        float4 hacc = make_float4(0.f, 0.f, 0.f, 0.f);
        #pragma unroll
        for (int hh = 0; hh < H; hh++) {
            float ald_d = __ldg(&ald[node * H + hh]);
            float mx = -1e30f;
            for (int j = beg + lane; j < end; j += 32) {
                float v = __ldg(&als[col[j] * H + hh]) + ald_d;
                v = v > 0.f ? v : 0.2f * v;
                mx = fmaxf(mx, v);
            }
            #pragma unroll
            for (int o = 16; o > 0; o >>= 1)
                mx = fmaxf(mx, __shfl_xor_sync(0xffffffffu, mx, o));
            float4 acc = make_float4(0.f, 0.f, 0.f, 0.f);
            float ssum = 0.f;
            for (int j0 = beg; j0 < end; j0 += 32) {
                int jj = j0 + lane;
                float ex = 0.f;
                int sc = 0;
                if (jj < end) {
                    sc = col[jj];
                    float v = __ldg(&als[sc * H + hh]) + ald_d;
                    v = v > 0.f ? v : 0.2f * v;
                    ex = __expf(v - mx);
                }
                ssum += ex;
                int cnt = end - j0; if (cnt > 32) cnt = 32;
                for (int t = 0; t < cnt; t++) {
                    float exb = __shfl_sync(0xffffffffu, ex, t);
                    int   sb  = __shfl_sync(0xffffffffu, sc, t);
                    float4 hv = ((const float4*)(h + ((size_t)sb * H + hh) * HID))[lane];
                    acc.x += exb * hv.x;
                    acc.y += exb * hv.y;
                    acc.z += exb * hv.z;
                    acc.w += exb * hv.w;
                }
            }
            #pragma unroll
            for (int o = 16; o > 0; o >>= 1)
                ssum += __shfl_xor_sync(0xffffffffu, ssum, o);
            float inv = 1.f / (ssum + 1e-16f);
            hacc.x += acc.x * inv; hacc.y += acc.y * inv;
            hacc.z += acc.z * inv; hacc.w += acc.w * inv;
        }
        int r = lane * 4;
        float4 bb = *(const float4*)&b[r];
        const float s = 1.f / (float)H;
        float4 v4 = make_float4(hacc.x * s + bb.x, hacc.y * s + bb.y,
                                hacc.z * s + bb.z, hacc.w * s + bb.w);
        *(float4*)&outbuf[(size_t)node * HID + r] = v4;
    }
}

// ---------------- segment mean pool (batch is sorted) ----------------
__global__ void pool_seg_kernel(const float* __restrict__ x3, const int* __restrict__ batch,
                                float* __restrict__ pool) {
    __shared__ int sbeg, send;
    int gph = blockIdx.x;
    int c = threadIdx.x;   // 128
    if (c == 0) {
        int lo = 0, hi = N_NODES;
        while (lo < hi) { int mid = (lo + hi) >> 1; if (batch[mid] < gph) lo = mid + 1; else hi = mid; }
        sbeg = lo;
        lo = 0; hi = N_NODES;
        while (lo < hi) { int mid = (lo + hi) >> 1; if (batch[mid] < gph + 1) lo = mid + 1; else hi = mid; }
        send = lo;
    }
    __syncthreads();
    float s = 0.f;
    for (int n = sbeg; n < send; n++) s += x3[(size_t)n * HID + c];
    float cf = (float)(send - sbeg); if (cf < 1.f) cf = 1.f;
    pool[gph * HID + c] = s / cf;
}

// ---------------- classifier head + log_softmax ----------------
__global__ void head_kernel(const float* __restrict__ pool,
                            const float* __restrict__ Wc, const float* __restrict__ bc,
                            float* __restrict__ out) {
    __shared__ float sl[NGRAPH][NCLS];
    __shared__ float lse[NGRAPH];
    int tid = threadIdx.x;               // 640 threads
    int g = tid / NCLS, k = tid % NCLS;
    float acc = bc[k];
    #pragma unroll 8
    for (int j = 0; j < HID; j++)
        acc += pool[(size_t)g * HID + j] * Wc[j * NCLS + k];
    sl[g][k] = acc;
    out[g * NCLS + k] = acc;             // logits
    __syncthreads();
    if (k == 0) {
        float mx = sl[g][0];
        #pragma unroll
        for (int j = 1; j < NCLS; j++) mx = fmaxf(mx, sl[g][j]);
        float s = 0.f;
        #pragma unroll
        for (int j = 0; j < NCLS; j++) s += expf(sl[g][j] - mx);
        lse[g] = mx + logf(s);
    }
    __syncthreads();
    out[NGRAPH * NCLS + g * NCLS + k] = sl[g][k] - lse[g];   // log_softmax
}

extern "C" void kernel_launch(void* const* d_in, const int* in_sizes, int n_in,
                              void* d_out, int out_size) {
    const float* x     = (const float*)d_in[0];
    const int*   ei    = (const int*)  d_in[1];
    const int*   batch = (const int*)  d_in[2];
    const float* W1  = (const float*)d_in[3];
    const float* a1s = (const float*)d_in[4];
    const float* a1d = (const float*)d_in[5];
    const float* b1  = (const float*)d_in[6];
    const float* W2  = (const float*)d_in[7];
    const float* a2s = (const float*)d_in[8];
    const float* a2d = (const float*)d_in[9];
    const float* b2  = (const float*)d_in[10];
    const float* W3  = (const float*)d_in[11];
    const float* a3s = (const float*)d_in[12];
    const float* a3d = (const float*)d_in[13];
    const float* b3  = (const float*)d_in[14];
    const float* Wc  = (const float*)d_in[15];
    const float* bc  = (const float*)d_in[16];
    float* out = (float*)d_out;

    float *h, *x1, *x2, *als, *ald, *x3, *pool;
    int *deg, *off, *cur, *col;
    cudaGetSymbolAddress((void**)&h,    g_h);
    cudaGetSymbolAddress((void**)&x1,   g_x1);
    cudaGetSymbolAddress((void**)&x2,   g_x2);
    cudaGetSymbolAddress((void**)&als,  g_als);
    cudaGetSymbolAddress((void**)&ald,  g_ald);
    cudaGetSymbolAddress((void**)&x3,   g_x3);
    cudaGetSymbolAddress((void**)&pool, g_pool);
    cudaGetSymbolAddress((void**)&deg,  g_deg);
    cudaGetSymbolAddress((void**)&off,  g_off);
    cudaGetSymbolAddress((void**)&cur,  g_cur);
    cudaGetSymbolAddress((void**)&col,  g_col);

    const int* src = ei;
    const int* dst = ei + N_EDGES;

    const int AGG_GRID_NH1 = (N_NODES * H1 * 32 + 255) / 256;   // (node,head) warps
    const int AGG_GRID_N   = (N_NODES * 32 + 255) / 256;        // per-node warps

    // ---- CSR build (by destination) ----
    fill_int_kernel<<<(N_NODES + 255) / 256, 256>>>(deg, 0, N_NODES);
    hist_kernel<<<(ETOT + 255) / 256, 256>>>(dst, deg);
    scan_kernel<<<1, 1024>>>(deg, off, cur);
    scatter_kernel<<<(ETOT + 255) / 256, 256>>>(src, dst, cur, col);

    // Layer 1: x1 = elu(gat(x) + b1)
    {
        dim3 grid(D1 / 128, (N_NODES + 127) / 128);
        mma_gemm_kernel<<<grid, 256>>>(x, W1, h, N_NODES, FIN, D1, a1s, a1d, als, ald, H1);
        gat_agg_kernel<H1, 1><<<AGG_GRID_NH1, 256>>>(off, col, als, ald, h, b1, nullptr, x1);
    }
    // Layer 2: x2 = elu(x1 + gat(x1) + b2)
    {
        dim3 grid(D1 / 128, (N_NODES + 127) / 128);
        mma_gemm_kernel<<<grid, 256>>>(x1, W2, h, N_NODES, D1, D1, a2s, a2d, als, ald, H1);
        gat_agg_kernel<H1, 2><<<AGG_GRID_NH1, 256>>>(off, col, als, ald, h, b2, x1, x2);
    }
    // Layer 3: x3 = mean-head gat(x2) + b3
    {
        dim3 grid((H3 * HID) / 128, (N_NODES + 127) / 128);
        mma_gemm_kernel<<<grid, 256>>>(x2, W3, h, N_NODES, D1, H3 * HID, a3s, a3d, als, ald, H3);
        gat_agg_kernel<H3, 3><<<AGG_GRID_N, 256>>>(off, col, als, ald, h, b3, nullptr, x3);
    }

    // Segment mean pool + head
    pool_seg_kernel<<<NGRAPH, HID>>>(x3, batch, pool);
    head_kernel<<<1, NGRAPH * NCLS>>>(pool, Wc, bc, out);
}